// round 13
// baseline (speedup 1.0000x reference)
#include <cuda_runtime.h>
#include <cuda_bf16.h>
#include <cstdint>

// ChannelBlockImportanceGate: forward value == hard top-k block mask.
// features [8,256,132,132] f32, enabled int32. BLOCK=8 -> 17x17=289 blocks,
// keep = 72. Ties: lower flat index wins (lax.top_k).
//
// R13: R12 machinery at 128 threads/CTA with 8-row chunks -> ~13.8 resident
// CTAs/SM (vs 8). More concurrent CTAs hide each other's memory-silent
// select phases, raising sustained DRAM pressure. Each chunk is exactly one
// block-row; fold order unchanged -> pooled sums bitwise identical.

#define HH   132
#define WW   132
#define NBX  17
#define NBLK 289
#define KEEP 72
#define NPIX (HH*WW)
#define NTHREADS 128
#define CHUNK_ROWS 8
#define NCHUNK 17
#define ROW_F4 33           // 132 floats = 33 float4 per row

__device__ __forceinline__ void cp_async16(void* smem_ptr, const void* gptr) {
    uint32_t s = (uint32_t)__cvta_generic_to_shared(smem_ptr);
    asm volatile("cp.async.cg.shared.global [%0], [%1], 16;\n"
                 :: "r"(s), "l"(gptr));
}
#define CP_COMMIT() asm volatile("cp.async.commit_group;\n" ::: "memory")
#define CP_WAIT1()  asm volatile("cp.async.wait_group 1;\n" ::: "memory")
#define CP_WAIT0()  asm volatile("cp.async.wait_group 0;\n" ::: "memory")

__global__ __launch_bounds__(NTHREADS, 16)
void gate_kernel(const float* __restrict__ in,
                 const int*  __restrict__ enabled,
                 float* __restrict__ out)
{
    const int bc = blockIdx.x;
    const long long base = (long long)bc * NPIX;
    const int tid  = threadIdx.x;
    const int warp = tid >> 5;
    const int lane = tid & 31;

    if (*enabled == 0) {
        float4 ones = make_float4(1.f, 1.f, 1.f, 1.f);
        float4* o4 = (float4*)(out + base);
        for (int p = tid; p < NPIX / 4; p += NTHREADS) o4[p] = ones;
        return;
    }

    __shared__ float4 buf[2][CHUNK_ROWS * ROW_F4];   // 2 x 4224 B staging
    __shared__ float  rbsl[CHUNK_ROWS * NBX];        // chunk-local partials
    __shared__ float  pooled[NBLK];
    __shared__ float  hardm[NBLK];
    __shared__ int    hist[32];
    __shared__ float  wmin[4], wmax[4];
    __shared__ float  s_minv, s_scale;
    __shared__ int    s_bb, s_chi, s_mcnt;
    __shared__ int    bblist[NBLK];

    if (tid < 32) hist[tid] = 0;
    if (tid == 0) s_mcnt = 0;

    const float4* src4 = (const float4*)(in + base);

    // ---- Phase A+B fused: double-buffered cp.async; per-chunk pooled fold.
    {
        int n4 = CHUNK_ROWS * ROW_F4;
        for (int i = tid; i < n4; i += NTHREADS)
            cp_async16(&buf[0][i], src4 + i);
        CP_COMMIT();
    }
    for (int c = 0; c < NCHUNK; c++) {
        int r0 = c * CHUNK_ROWS;
        int nr = min(CHUNK_ROWS, HH - r0);
        if (c + 1 < NCHUNK) {
            int r0n = (c + 1) * CHUNK_ROWS;
            int nrn = min(CHUNK_ROWS, HH - r0n);
            int n4  = nrn * ROW_F4;
            const float4* g = src4 + r0n * ROW_F4;
            float4* b = buf[(c + 1) & 1];
            for (int i = tid; i < n4; i += NTHREADS)
                cp_async16(&b[i], g + i);
            CP_COMMIT();
            CP_WAIT1();
        } else {
            CP_WAIT0();
        }
        __syncthreads();          // staged data visible; prior fold done

        // consume chunk c: per-(local row, bx) partial, canonical tree
        const float* bf = (const float*)buf[c & 1];
        int tasks = nr * NBX;
        for (int t = tid; t < tasks; t += NTHREADS) {
            int rl = t / NBX;
            int bx = t - rl * NBX;
            const float* row = bf + rl * WW;
            float4 a = *(const float4*)(row + bx * 8);
            float4 b4;
            if (bx < 16) b4 = *(const float4*)(row + bx * 8 + 4);
            else         b4 = make_float4(0.f, 0.f, 0.f, 0.f);
            rbsl[rl * NBX + bx] =
                  ((fabsf(a.x) + fabsf(b4.x)) + (fabsf(a.z) + fabsf(b4.z)))
                + ((fabsf(a.y) + fabsf(b4.y)) + (fabsf(a.w) + fabsf(b4.w)));
        }
        __syncthreads();          // rbsl complete for chunk c

        // fold: chunk c == block-row c; rows in increasing order (bitwise
        // identical to the passing kernels' Phase B). Tail has 4 valid rows.
        if (tid < NBX) {
            int nr2 = (c == NCHUNK - 1) ? 4 : 8;
            float s = 0.0f;
            #pragma unroll
            for (int r = 0; r < 8; r++)
                if (r < nr2) s += rbsl[r * NBX + tid];
            pooled[c * NBX + tid] = s;
        }
        // fold protected by the next iteration's first barrier
    }
    __syncthreads();              // last fold visible

    // ---- min/max over pooled
    float lmin = 3.4e38f, lmax = -3.4e38f;
    for (int b = tid; b < NBLK; b += NTHREADS) {
        float s = pooled[b];
        lmin = fminf(lmin, s);
        lmax = fmaxf(lmax, s);
    }
    #pragma unroll
    for (int off = 16; off > 0; off >>= 1) {
        lmin = fminf(lmin, __shfl_down_sync(0xffffffffu, lmin, off));
        lmax = fmaxf(lmax, __shfl_down_sync(0xffffffffu, lmax, off));
    }
    if (lane == 0) { wmin[warp] = lmin; wmax[warp] = lmax; }
    __syncthreads();

    // ---- warp 0: global min/max -> bin scale
    if (warp == 0) {
        float mn = (lane < 4) ? wmin[lane] : 3.4e38f;
        float mx = (lane < 4) ? wmax[lane] : -3.4e38f;
        #pragma unroll
        for (int off = 2; off > 0; off >>= 1) {
            mn = fminf(mn, __shfl_down_sync(0xffffffffu, mn, off));
            mx = fmaxf(mx, __shfl_down_sync(0xffffffffu, mx, off));
        }
        if (lane == 0) {
            float r = mx - mn;
            s_minv  = mn;
            s_scale = (r > 0.0f) ? (32.0f / r) : 0.0f;
        }
    }
    __syncthreads();

    // ---- histogram
    {
        float minv = s_minv, scale = s_scale;
        for (int b = tid; b < NBLK; b += NTHREADS) {
            int bin = min((int)((pooled[b] - minv) * scale), 31);
            atomicAdd(&hist[bin], 1);
        }
    }
    __syncthreads();

    // ---- warp 0: suffix scan -> boundary bin bb, count strictly above (chi)
    if (warp == 0) {
        int cge = hist[lane];
        #pragma unroll
        for (int off = 1; off < 32; off <<= 1) {
            int t = __shfl_down_sync(0xffffffffu, cge, off);
            if (lane + off < 32) cge += t;
        }
        int cgt = __shfl_down_sync(0xffffffffu, cge, 1);
        if (lane == 31) cgt = 0;
        if (cgt < KEEP && cge >= KEEP) { s_bb = lane; s_chi = cgt; }
    }
    __syncthreads();

    // ---- classify; collect boundary-bin items
    {
        float minv = s_minv, scale = s_scale;
        int bb = s_bb;
        for (int b = tid; b < NBLK; b += NTHREADS) {
            int bin = min((int)((pooled[b] - minv) * scale), 31);
            if (bin > bb)      hardm[b] = 1.0f;
            else if (bin < bb) hardm[b] = 0.0f;
            else               bblist[atomicAdd(&s_mcnt, 1)] = b;
        }
    }
    __syncthreads();

    // ---- exact rank inside boundary bin (tie: lower index wins)
    {
        int m = s_mcnt;
        int budget = KEEP - s_chi;
        for (int it = tid; it < m; it += NTHREADS) {
            int i = bblist[it];
            float vi = pooled[i];
            int c = 0;
            for (int j = 0; j < m; j++) {
                int jj = bblist[j];
                float vj = pooled[jj];
                c += (vj > vi) || (vj == vi && jj < i);
            }
            hardm[i] = (c < budget) ? 1.0f : 0.0f;
        }
    }
    __syncthreads();

    // ---- Phase D: expand to pixels, float4 stores (4 warps over 17 rows)
    for (int by = warp; by < NBX; by += 4) {
        float  mv  = hardm[by * NBX + (lane >> 1)];
        float  m16 = hardm[by * NBX + 16];
        float4 v4  = make_float4(mv, mv, mv, mv);
        float4 v16 = make_float4(m16, m16, m16, m16);
        int ylim = min(HH - by * 8, 8);
        float* obase = out + base + (by * 8) * WW;
        for (int r = 0; r < ylim; r++) {
            float* orow = obase + r * WW;
            *(float4*)(orow + lane * 4) = v4;
            if (lane == 0) *(float4*)(orow + 128) = v16;
        }
    }
}

extern "C" void kernel_launch(void* const* d_in, const int* in_sizes, int n_in,
                              void* d_out, int out_size)
{
    const float* features = (const float*)d_in[0];
    const int*   enabled  = (const int*)d_in[1];
    float* out = (float*)d_out;

    const int n_channels = out_size / NPIX;   // 2048
    gate_kernel<<<n_channels, NTHREADS>>>(features, enabled, out);
}

// round 14
// speedup vs baseline: 1.0607x; 1.0607x over previous
#include <cuda_runtime.h>
#include <cuda_bf16.h>
#include <cstdint>

// ChannelBlockImportanceGate: forward value == hard top-k block mask.
// features [8,256,132,132] f32, enabled int32. BLOCK=8 -> 17x17=289 blocks,
// keep = 72. Ties: lower flat index wins (lax.top_k).
//
// R14: R12 (best known, 52.1us) with Phase D switched from per-thread STG
// to bulk async stores: 17 block-row images built in the staging buffer,
// then one cp.async.bulk (528B) per pixel row -- zero L1tex STG wavefronts,
// full-row write bursts. Everything upstream byte-identical to R12.

#define HH   132
#define WW   132
#define NBX  17
#define NBLK 289
#define KEEP 72
#define NPIX (HH*WW)
#define NTHREADS 256
#define CHUNK_ROWS 16
#define NCHUNK 9
#define ROW_F4 33           // 132 floats = 33 float4 per row
#define ROW_BYTES (WW*4)    // 528

__device__ __forceinline__ void cp_async16(void* smem_ptr, const void* gptr) {
    uint32_t s = (uint32_t)__cvta_generic_to_shared(smem_ptr);
    asm volatile("cp.async.cg.shared.global [%0], [%1], 16;\n"
                 :: "r"(s), "l"(gptr));
}
#define CP_COMMIT() asm volatile("cp.async.commit_group;\n" ::: "memory")
#define CP_WAIT1()  asm volatile("cp.async.wait_group 1;\n" ::: "memory")
#define CP_WAIT0()  asm volatile("cp.async.wait_group 0;\n" ::: "memory")

__device__ __forceinline__ void bulk_store(void* gptr, const void* smem_ptr, int bytes) {
    uint32_t s = (uint32_t)__cvta_generic_to_shared(smem_ptr);
    asm volatile("cp.async.bulk.global.shared::cta.bulk_group [%0], [%1], %2;\n"
                 :: "l"(gptr), "r"(s), "r"(bytes) : "memory");
}
#define BULK_COMMIT() asm volatile("cp.async.bulk.commit_group;\n" ::: "memory")
#define BULK_WAIT0()  asm volatile("cp.async.bulk.wait_group 0;\n" ::: "memory")
#define FENCE_ASYNC() asm volatile("fence.proxy.async.shared::cta;\n" ::: "memory")

__global__ __launch_bounds__(NTHREADS)
void gate_kernel(const float* __restrict__ in,
                 const int*  __restrict__ enabled,
                 float* __restrict__ out)
{
    const int bc = blockIdx.x;
    const long long base = (long long)bc * NPIX;
    const int tid  = threadIdx.x;
    const int warp = tid >> 5;
    const int lane = tid & 31;

    if (*enabled == 0) {
        float4 ones = make_float4(1.f, 1.f, 1.f, 1.f);
        float4* o4 = (float4*)(out + base);
        for (int p = tid; p < NPIX / 4; p += NTHREADS) o4[p] = ones;
        return;
    }

    __shared__ float4 buf[2][CHUNK_ROWS * ROW_F4];   // staging; reused as rowpat
    __shared__ float  rbsl[CHUNK_ROWS * NBX];        // chunk-local partials
    __shared__ float  pooled[NBLK];
    __shared__ float  hardm[NBLK];
    __shared__ int    hist[32];
    __shared__ float  wmin[8], wmax[8];
    __shared__ float  s_minv, s_scale;
    __shared__ int    s_bb, s_chi, s_mcnt;
    __shared__ int    bblist[NBLK];

    if (tid < 32) hist[tid] = 0;
    if (tid == 0) s_mcnt = 0;

    const float4* src4 = (const float4*)(in + base);

    // ---- Phase A+B fused: double-buffered cp.async; per-chunk pooled fold.
    {
        int n4 = CHUNK_ROWS * ROW_F4;
        for (int i = tid; i < n4; i += NTHREADS)
            cp_async16(&buf[0][i], src4 + i);
        CP_COMMIT();
    }
    for (int c = 0; c < NCHUNK; c++) {
        int r0 = c * CHUNK_ROWS;
        int nr = min(CHUNK_ROWS, HH - r0);
        if (c + 1 < NCHUNK) {
            int r0n = (c + 1) * CHUNK_ROWS;
            int nrn = min(CHUNK_ROWS, HH - r0n);
            int n4  = nrn * ROW_F4;
            const float4* g = src4 + r0n * ROW_F4;
            float4* b = buf[(c + 1) & 1];
            for (int i = tid; i < n4; i += NTHREADS)
                cp_async16(&b[i], g + i);
            CP_COMMIT();
            CP_WAIT1();
        } else {
            CP_WAIT0();
        }
        __syncthreads();          // staged data visible; prior fold done

        // consume chunk c: per-(local row, bx) partial, canonical tree
        const float* bf = (const float*)buf[c & 1];
        int tasks = nr * NBX;
        for (int t = tid; t < tasks; t += NTHREADS) {
            int rl = t / NBX;
            int bx = t - rl * NBX;
            const float* row = bf + rl * WW;
            float4 a = *(const float4*)(row + bx * 8);
            float4 b4;
            if (bx < 16) b4 = *(const float4*)(row + bx * 8 + 4);
            else         b4 = make_float4(0.f, 0.f, 0.f, 0.f);
            rbsl[rl * NBX + bx] =
                  ((fabsf(a.x) + fabsf(b4.x)) + (fabsf(a.z) + fabsf(b4.z)))
                + ((fabsf(a.y) + fabsf(b4.y)) + (fabsf(a.w) + fabsf(b4.w)));
        }
        __syncthreads();          // rbsl complete for chunk c

        // pooled fold: chunk c holds block-rows 2c, 2c+1 (tail: block-row 16,
        // 4 valid rows). Increasing-row order -> bitwise identical sums.
        int nb = (c == NCHUNK - 1) ? NBX : 2 * NBX;
        if (tid < nb) {
            int lr = tid / NBX;
            int bx = tid - lr * NBX;
            int nr2 = (c == NCHUNK - 1) ? 4 : 8;
            float s = 0.0f;
            #pragma unroll
            for (int r = 0; r < 8; r++)
                if (r < nr2) s += rbsl[(lr * 8 + r) * NBX + bx];
            pooled[c * 34 + tid] = s;
        }
    }
    __syncthreads();              // last fold visible

    // ---- min/max over pooled
    float lmin = 3.4e38f, lmax = -3.4e38f;
    for (int b = tid; b < NBLK; b += NTHREADS) {
        float s = pooled[b];
        lmin = fminf(lmin, s);
        lmax = fmaxf(lmax, s);
    }
    #pragma unroll
    for (int off = 16; off > 0; off >>= 1) {
        lmin = fminf(lmin, __shfl_down_sync(0xffffffffu, lmin, off));
        lmax = fmaxf(lmax, __shfl_down_sync(0xffffffffu, lmax, off));
    }
    if (lane == 0) { wmin[warp] = lmin; wmax[warp] = lmax; }
    __syncthreads();

    // ---- warp 0: global min/max -> bin scale
    if (warp == 0) {
        float mn = (lane < 8) ? wmin[lane] : 3.4e38f;
        float mx = (lane < 8) ? wmax[lane] : -3.4e38f;
        #pragma unroll
        for (int off = 4; off > 0; off >>= 1) {
            mn = fminf(mn, __shfl_down_sync(0xffffffffu, mn, off));
            mx = fmaxf(mx, __shfl_down_sync(0xffffffffu, mx, off));
        }
        if (lane == 0) {
            float r = mx - mn;
            s_minv  = mn;
            s_scale = (r > 0.0f) ? (32.0f / r) : 0.0f;
        }
    }
    __syncthreads();

    // ---- histogram
    {
        float minv = s_minv, scale = s_scale;
        for (int b = tid; b < NBLK; b += NTHREADS) {
            int bin = min((int)((pooled[b] - minv) * scale), 31);
            atomicAdd(&hist[bin], 1);
        }
    }
    __syncthreads();

    // ---- warp 0: suffix scan -> boundary bin bb, count strictly above (chi)
    if (warp == 0) {
        int cge = hist[lane];
        #pragma unroll
        for (int off = 1; off < 32; off <<= 1) {
            int t = __shfl_down_sync(0xffffffffu, cge, off);
            if (lane + off < 32) cge += t;
        }
        int cgt = __shfl_down_sync(0xffffffffu, cge, 1);
        if (lane == 31) cgt = 0;
        if (cgt < KEEP && cge >= KEEP) { s_bb = lane; s_chi = cgt; }
    }
    __syncthreads();

    // ---- classify; collect boundary-bin items
    {
        float minv = s_minv, scale = s_scale;
        int bb = s_bb;
        for (int b = tid; b < NBLK; b += NTHREADS) {
            int bin = min((int)((pooled[b] - minv) * scale), 31);
            if (bin > bb)      hardm[b] = 1.0f;
            else if (bin < bb) hardm[b] = 0.0f;
            else               bblist[atomicAdd(&s_mcnt, 1)] = b;
        }
    }
    __syncthreads();

    // ---- exact rank inside boundary bin (tie: lower index wins)
    {
        int m = s_mcnt;
        int budget = KEEP - s_chi;
        for (int it = tid; it < m; it += NTHREADS) {
            int i = bblist[it];
            float vi = pooled[i];
            int c = 0;
            for (int j = 0; j < m; j++) {
                int jj = bblist[j];
                float vj = pooled[jj];
                c += (vj > vi) || (vj == vi && jj < i);
            }
            hardm[i] = (c < budget) ? 1.0f : 0.0f;
        }
    }
    __syncthreads();

    // ---- Phase D: build 17 block-row images in smem, then one 528B bulk
    // async store per pixel row (no per-thread STG, no L1 store wavefronts).
    float4* rowpat = (float4*)buf;             // 17*33 float4 = 8976 B
    for (int i = tid; i < NBX * ROW_F4; i += NTHREADS) {
        int by = i / ROW_F4;
        int x4 = i - by * ROW_F4;
        float v = hardm[by * NBX + (x4 >> 1)]; // 4 pixels never straddle a block
        rowpat[i] = make_float4(v, v, v, v);
    }
    FENCE_ASYNC();                             // make smem visible to async proxy
    __syncthreads();

    if (tid < HH) {
        int y = tid;                           // pixel row
        const void* src = &rowpat[(y >> 3) * ROW_F4];
        void* dst = out + base + y * WW;
        bulk_store(dst, src, ROW_BYTES);
        BULK_COMMIT();
        BULK_WAIT0();                          // stores complete before exit
    }
}

extern "C" void kernel_launch(void* const* d_in, const int* in_sizes, int n_in,
                              void* d_out, int out_size)
{
    const float* features = (const float*)d_in[0];
    const int*   enabled  = (const int*)d_in[1];
    float* out = (float*)d_out;

    const int n_channels = out_size / NPIX;   // 2048
    gate_kernel<<<n_channels, NTHREADS>>>(features, enabled, out);
}

// round 15
// speedup vs baseline: 1.0653x; 1.0043x over previous
#include <cuda_runtime.h>
#include <cuda_bf16.h>
#include <cstdint>

// ChannelBlockImportanceGate: forward value == hard top-k block mask.
// features [8,256,132,132] f32, enabled int32. BLOCK=8 -> 17x17=289 blocks,
// keep = 72. Ties: lower flat index wins (lax.top_k).
//
// R15: R12 (best known, 52.06us) + evict-first streaming stores (__stcs) in
// Phase D: written mask data has zero reuse, so keep it from occupying L2
// and perturbing the read stream. Everything else byte-identical to R12.

#define HH   132
#define WW   132
#define NBX  17
#define NBLK 289
#define KEEP 72
#define NPIX (HH*WW)
#define NTHREADS 256
#define CHUNK_ROWS 16
#define NCHUNK 9
#define ROW_F4 33           // 132 floats = 33 float4 per row

__device__ __forceinline__ void cp_async16(void* smem_ptr, const void* gptr) {
    uint32_t s = (uint32_t)__cvta_generic_to_shared(smem_ptr);
    asm volatile("cp.async.cg.shared.global [%0], [%1], 16;\n"
                 :: "r"(s), "l"(gptr));
}
#define CP_COMMIT() asm volatile("cp.async.commit_group;\n" ::: "memory")
#define CP_WAIT1()  asm volatile("cp.async.wait_group 1;\n" ::: "memory")
#define CP_WAIT0()  asm volatile("cp.async.wait_group 0;\n" ::: "memory")

__global__ __launch_bounds__(NTHREADS)
void gate_kernel(const float* __restrict__ in,
                 const int*  __restrict__ enabled,
                 float* __restrict__ out)
{
    const int bc = blockIdx.x;
    const long long base = (long long)bc * NPIX;
    const int tid  = threadIdx.x;
    const int warp = tid >> 5;
    const int lane = tid & 31;

    if (*enabled == 0) {
        float4 ones = make_float4(1.f, 1.f, 1.f, 1.f);
        float4* o4 = (float4*)(out + base);
        for (int p = tid; p < NPIX / 4; p += NTHREADS) __stcs(o4 + p, ones);
        return;
    }

    __shared__ float4 buf[2][CHUNK_ROWS * ROW_F4];   // 16.9 KB staging
    __shared__ float  rbsl[CHUNK_ROWS * NBX];        // chunk-local partials
    __shared__ float  pooled[NBLK];
    __shared__ float  hardm[NBLK];
    __shared__ int    hist[32];
    __shared__ float  wmin[8], wmax[8];
    __shared__ float  s_minv, s_scale;
    __shared__ int    s_bb, s_chi, s_mcnt;
    __shared__ int    bblist[NBLK];

    if (tid < 32) hist[tid] = 0;
    if (tid == 0) s_mcnt = 0;

    const float4* src4 = (const float4*)(in + base);

    // ---- Phase A+B fused: double-buffered cp.async; per-chunk pooled fold.
    {
        int n4 = CHUNK_ROWS * ROW_F4;
        for (int i = tid; i < n4; i += NTHREADS)
            cp_async16(&buf[0][i], src4 + i);
        CP_COMMIT();
    }
    for (int c = 0; c < NCHUNK; c++) {
        int r0 = c * CHUNK_ROWS;
        int nr = min(CHUNK_ROWS, HH - r0);
        if (c + 1 < NCHUNK) {
            int r0n = (c + 1) * CHUNK_ROWS;
            int nrn = min(CHUNK_ROWS, HH - r0n);
            int n4  = nrn * ROW_F4;
            const float4* g = src4 + r0n * ROW_F4;
            float4* b = buf[(c + 1) & 1];
            for (int i = tid; i < n4; i += NTHREADS)
                cp_async16(&b[i], g + i);
            CP_COMMIT();
            CP_WAIT1();
        } else {
            CP_WAIT0();
        }
        __syncthreads();          // staged data visible; prior fold done

        // consume chunk c: per-(local row, bx) partial, canonical tree
        const float* bf = (const float*)buf[c & 1];
        int tasks = nr * NBX;
        for (int t = tid; t < tasks; t += NTHREADS) {
            int rl = t / NBX;
            int bx = t - rl * NBX;
            const float* row = bf + rl * WW;
            float4 a = *(const float4*)(row + bx * 8);
            float4 b4;
            if (bx < 16) b4 = *(const float4*)(row + bx * 8 + 4);
            else         b4 = make_float4(0.f, 0.f, 0.f, 0.f);
            rbsl[rl * NBX + bx] =
                  ((fabsf(a.x) + fabsf(b4.x)) + (fabsf(a.z) + fabsf(b4.z)))
                + ((fabsf(a.y) + fabsf(b4.y)) + (fabsf(a.w) + fabsf(b4.w)));
        }
        __syncthreads();          // rbsl complete for chunk c

        // pooled fold: chunk c holds block-rows 2c (rows 0..7) and 2c+1
        // (rows 8..15); tail chunk 8 holds block-row 16 (4 valid rows).
        // Increasing-row order -> bitwise identical to all passing rounds.
        int nb = (c == NCHUNK - 1) ? NBX : 2 * NBX;
        if (tid < nb) {
            int lr = tid / NBX;
            int bx = tid - lr * NBX;
            int nr2 = (c == NCHUNK - 1) ? 4 : 8;
            float s = 0.0f;
            #pragma unroll
            for (int r = 0; r < 8; r++)
                if (r < nr2) s += rbsl[(lr * 8 + r) * NBX + bx];
            pooled[c * 34 + tid] = s;
        }
        // fold protected by the next iteration's first barrier
    }
    __syncthreads();              // last fold visible

    // ---- min/max over pooled
    float lmin = 3.4e38f, lmax = -3.4e38f;
    for (int b = tid; b < NBLK; b += NTHREADS) {
        float s = pooled[b];
        lmin = fminf(lmin, s);
        lmax = fmaxf(lmax, s);
    }
    #pragma unroll
    for (int off = 16; off > 0; off >>= 1) {
        lmin = fminf(lmin, __shfl_down_sync(0xffffffffu, lmin, off));
        lmax = fmaxf(lmax, __shfl_down_sync(0xffffffffu, lmax, off));
    }
    if (lane == 0) { wmin[warp] = lmin; wmax[warp] = lmax; }
    __syncthreads();

    // ---- warp 0: global min/max -> bin scale
    if (warp == 0) {
        float mn = (lane < 8) ? wmin[lane] : 3.4e38f;
        float mx = (lane < 8) ? wmax[lane] : -3.4e38f;
        #pragma unroll
        for (int off = 4; off > 0; off >>= 1) {
            mn = fminf(mn, __shfl_down_sync(0xffffffffu, mn, off));
            mx = fmaxf(mx, __shfl_down_sync(0xffffffffu, mx, off));
        }
        if (lane == 0) {
            float r = mx - mn;
            s_minv  = mn;
            s_scale = (r > 0.0f) ? (32.0f / r) : 0.0f;
        }
    }
    __syncthreads();

    // ---- histogram
    {
        float minv = s_minv, scale = s_scale;
        for (int b = tid; b < NBLK; b += NTHREADS) {
            int bin = min((int)((pooled[b] - minv) * scale), 31);
            atomicAdd(&hist[bin], 1);
        }
    }
    __syncthreads();

    // ---- warp 0: suffix scan -> boundary bin bb, count strictly above (chi)
    if (warp == 0) {
        int cge = hist[lane];
        #pragma unroll
        for (int off = 1; off < 32; off <<= 1) {
            int t = __shfl_down_sync(0xffffffffu, cge, off);
            if (lane + off < 32) cge += t;
        }
        int cgt = __shfl_down_sync(0xffffffffu, cge, 1);
        if (lane == 31) cgt = 0;
        if (cgt < KEEP && cge >= KEEP) { s_bb = lane; s_chi = cgt; }
    }
    __syncthreads();

    // ---- classify; collect boundary-bin items
    {
        float minv = s_minv, scale = s_scale;
        int bb = s_bb;
        for (int b = tid; b < NBLK; b += NTHREADS) {
            int bin = min((int)((pooled[b] - minv) * scale), 31);
            if (bin > bb)      hardm[b] = 1.0f;
            else if (bin < bb) hardm[b] = 0.0f;
            else               bblist[atomicAdd(&s_mcnt, 1)] = b;
        }
    }
    __syncthreads();

    // ---- exact rank inside boundary bin (tie: lower index wins)
    {
        int m = s_mcnt;
        int budget = KEEP - s_chi;
        for (int it = tid; it < m; it += NTHREADS) {
            int i = bblist[it];
            float vi = pooled[i];
            int c = 0;
            for (int j = 0; j < m; j++) {
                int jj = bblist[j];
                float vj = pooled[jj];
                c += (vj > vi) || (vj == vi && jj < i);
            }
            hardm[i] = (c < budget) ? 1.0f : 0.0f;
        }
    }
    __syncthreads();

    // ---- Phase D: expand to pixels; evict-first streaming float4 stores
    for (int by = warp; by < NBX; by += 8) {
        float  mv  = hardm[by * NBX + (lane >> 1)];
        float  m16 = hardm[by * NBX + 16];
        float4 v4  = make_float4(mv, mv, mv, mv);
        float4 v16 = make_float4(m16, m16, m16, m16);
        int ylim = min(HH - by * 8, 8);
        float* obase = out + base + (by * 8) * WW;
        for (int r = 0; r < ylim; r++) {
            float* orow = obase + r * WW;
            __stcs((float4*)(orow + lane * 4), v4);
            if (lane == 0) __stcs((float4*)(orow + 128), v16);
        }
    }
}

extern "C" void kernel_launch(void* const* d_in, const int* in_sizes, int n_in,
                              void* d_out, int out_size)
{
    const float* features = (const float*)d_in[0];
    const int*   enabled  = (const int*)d_in[1];
    float* out = (float*)d_out;

    const int n_channels = out_size / NPIX;   // 2048
    gate_kernel<<<n_channels, NTHREADS>>>(features, enabled, out);
}